// round 15
// baseline (speedup 1.0000x reference)
#include <cuda_runtime.h>
#include <cuda_bf16.h>

#define C_CLASSES 5
#define NREP 4   // target-table replicas, stride 8 words

__device__ double   g_acc[2];   // [0]=num, [1]=den. Zero-init at load; last block resets.
__device__ unsigned g_count;    // blocks-done counter. Zero-init; last block resets.

// ip(x) = alpha + beta*x + sum_k gamma[k]*|x-k|  (exact piecewise-linear interp)
__device__ __forceinline__ void owe_elem(float x, int t,
                                         float al, float be,
                                         float g0, float g1, float g2,
                                         float g3, float g4,
                                         const float* __restrict__ tp,
                                         const float* __restrict__ tw,
                                         float& num, float& den) {
    float ip = fmaf(be, x, al);
    ip = fmaf(g0, fabsf(x),        ip);
    ip = fmaf(g1, fabsf(x - 1.0f), ip);
    ip = fmaf(g2, fabsf(x - 2.0f), ip);
    ip = fmaf(g3, fabsf(x - 3.0f), ip);
    ip = fmaf(g4, fabsf(x - 4.0f), ip);
    float p = tp[t];
    float w = tw[t];
    float d = ip - p;
    num = fmaf(d * d, w, num);
    den += w;
}

#define ELEM4(xv, tv, nm, dn) \
    owe_elem((xv).x, (tv).x, al, be, g0, g1, g2, g3, g4, tp, tw, nm, dn); \
    owe_elem((xv).y, (tv).y, al, be, g0, g1, g2, g3, g4, tp, tw, nm, dn); \
    owe_elem((xv).z, (tv).z, al, be, g0, g1, g2, g3, g4, tp, tw, nm, dn); \
    owe_elem((xv).w, (tv).w, al, be, g0, g1, g2, g3, g4, tp, tw, nm, dn);

__global__ void __launch_bounds__(128, 12)
owe_kernel(const float4* __restrict__ inp4,
           const int4*  __restrict__ tgt4,
           const float* __restrict__ weight,
           const float* __restrict__ dist,
           int n4,
           const float* __restrict__ inp_tail,
           const int*   __restrict__ tgt_tail,
           int tail_start, int n_total,
           float* __restrict__ out) {
    __shared__ float s_coef[8];        // alpha, beta, g0..g4
    __shared__ float s_tp[NREP * 8];   // pcnl[t], replicated
    __shared__ float s_tw[NREP * 8];   // weight[t], replicated

    if (threadIdx.x == 0) {
        float ds[C_CLASSES], cs[C_CLASSES];
        float ext[C_CLASSES + 2], s[C_CLASSES + 1];
        float c = 0.f;
        #pragma unroll
        for (int k = 0; k < C_CLASSES; k++) { ds[k] = dist[k]; c += ds[k]; cs[k] = c; }
        float inv = 1.0f / (2.0f * cs[C_CLASSES - 1] - ds[0] - ds[C_CLASSES - 1]);
        ext[0] = -1.0f / (float)(C_CLASSES - 1);
        #pragma unroll
        for (int k = 0; k < C_CLASSES; k++)
            ext[k + 1] = (2.0f * cs[k] - ds[k] - ds[0]) * inv;
        ext[C_CLASSES + 1] = (float)C_CLASSES / (float)(C_CLASSES - 1);
        #pragma unroll
        for (int j = 0; j <= C_CLASSES; j++)
            s[j] = ext[j + 1] - ext[j];
        float gs = 0.0f;
        #pragma unroll
        for (int k = 0; k < C_CLASSES; k++) {
            float g = 0.5f * (s[k + 1] - s[k]);
            s_coef[2 + k] = g;
            gs += g * (float)k;
        }
        s_coef[1] = 0.5f * (s[0] + s[C_CLASSES]);
        s_coef[0] = ext[1] - gs;
        #pragma unroll
        for (int r = 0; r < NREP; r++) {
            #pragma unroll
            for (int k = 0; k < C_CLASSES; k++) {
                s_tp[r * 8 + k] = ext[k + 1];
                s_tw[r * 8 + k] = weight[k];
            }
        }
    }
    __syncthreads();

    const float al = s_coef[0];
    const float be = s_coef[1];
    const float g0 = s_coef[2];
    const float g1 = s_coef[3];
    const float g2 = s_coef[4];
    const float g3 = s_coef[5];
    const float g4 = s_coef[6];

    const int rep = (threadIdx.x & (NREP - 1)) * 8;
    const float* __restrict__ tp = s_tp + rep;
    const float* __restrict__ tw = s_tw + rep;

    // 4 independent accumulator pairs (one per in-flight vec4 pair).
    float num0 = 0.0f, num1 = 0.0f, num2 = 0.0f, num3 = 0.0f;
    float den0 = 0.0f, den1 = 0.0f, den2 = 0.0f, den3 = 0.0f;

    int tid    = blockIdx.x * blockDim.x + threadIdx.x;
    int stride = gridDim.x * blockDim.x;

    int i = tid;
    // Unroll x4: 8 LDG.128 front-batched (MLP_p1 = 8).
    for (; i + 3 * stride < n4; i += 4 * stride) {
        float4 x0 = inp4[i];
        float4 x1 = inp4[i + stride];
        float4 x2 = inp4[i + 2 * stride];
        float4 x3 = inp4[i + 3 * stride];
        int4   t0 = tgt4[i];
        int4   t1 = tgt4[i + stride];
        int4   t2 = tgt4[i + 2 * stride];
        int4   t3 = tgt4[i + 3 * stride];
        ELEM4(x0, t0, num0, den0)
        ELEM4(x1, t1, num1, den1)
        ELEM4(x2, t2, num2, den2)
        ELEM4(x3, t3, num3, den3)
    }
    for (; i < n4; i += stride) {
        float4 x0 = inp4[i];
        int4   t0 = tgt4[i];
        ELEM4(x0, t0, num0, den0)
    }
    for (int jj = tail_start + tid; jj < n_total; jj += stride) {
        owe_elem(inp_tail[jj], tgt_tail[jj], al, be, g0, g1, g2, g3, g4,
                 tp, tw, num0, den0);
    }

    float num = (num0 + num1) + (num2 + num3);
    float den = (den0 + den1) + (den2 + den3);

    // Warp reduction
    #pragma unroll
    for (int off = 16; off > 0; off >>= 1) {
        num += __shfl_down_sync(0xFFFFFFFFu, num, off);
        den += __shfl_down_sync(0xFFFFFFFFu, den, off);
    }

    // Block reduction (4 warps/block)
    __shared__ float s_num[4];
    __shared__ float s_den[4];
    int lane = threadIdx.x & 31;
    int warp = threadIdx.x >> 5;
    if (lane == 0) { s_num[warp] = num; s_den[warp] = den; }
    __syncthreads();
    if (warp == 0) {
        float bn = (lane < (blockDim.x >> 5)) ? s_num[lane] : 0.0f;
        float bd = (lane < (blockDim.x >> 5)) ? s_den[lane] : 0.0f;
        #pragma unroll
        for (int off = 2; off > 0; off >>= 1) {
            bn += __shfl_down_sync(0xFFFFFFFFu, bn, off);
            bd += __shfl_down_sync(0xFFFFFFFFu, bd, off);
        }
        if (lane == 0) {
            atomicAdd(&g_acc[0], (double)bn);
            atomicAdd(&g_acc[1], (double)bd);
            __threadfence();
            unsigned done = atomicAdd(&g_count, 1u);
            if (done == gridDim.x - 1) {
                double fn = __longlong_as_double(
                    atomicExch((unsigned long long*)&g_acc[0], 0ULL));
                double fd = __longlong_as_double(
                    atomicExch((unsigned long long*)&g_acc[1], 0ULL));
                out[0] = (float)(fn / fd);
                atomicExch(&g_count, 0u);
            }
        }
    }
}

extern "C" void kernel_launch(void* const* d_in, const int* in_sizes, int n_in,
                              void* d_out, int out_size) {
    const float* inp  = (const float*)d_in[0];
    const int*   tgt  = (const int*)d_in[1];
    const float* wgt  = (const float*)d_in[2];
    const float* dist = (const float*)d_in[3];
    float* out = (float*)d_out;

    int n  = in_sizes[0];
    int n4 = n >> 2;
    int tail_start = n4 << 2;

    const int threads = 128;
    int blocks = 148 * 12;  // 1776 blocks: same 48 warps/SM as R9, finer granularity
    int max_useful = (n4 + threads - 1) / threads;
    if (blocks > max_useful && max_useful > 0) blocks = max_useful;
    if (blocks < 1) blocks = 1;

    owe_kernel<<<blocks, threads>>>((const float4*)inp, (const int4*)tgt,
                                    wgt, dist, n4, inp, tgt, tail_start, n, out);
}

// round 16
// speedup vs baseline: 1.1498x; 1.1498x over previous
#include <cuda_runtime.h>
#include <cuda_bf16.h>

#define C_CLASSES 5
#define NREP 4   // target-table replicas, stride 8 words

__device__ double   g_acc[2];   // [0]=num, [1]=den. Zero-init at load; last block resets.
__device__ unsigned g_count;    // blocks-done counter. Zero-init; last block resets.

// ip(x) = alpha + beta*x + sum_k gamma[k]*|x-k|  (exact piecewise-linear interp)
__device__ __forceinline__ void owe_elem(float x, int t,
                                         float al, float be,
                                         float g0, float g1, float g2,
                                         float g3, float g4,
                                         const float* __restrict__ tp,
                                         const float* __restrict__ tw,
                                         float& num, float& den) {
    float ip = fmaf(be, x, al);
    ip = fmaf(g0, fabsf(x),        ip);
    ip = fmaf(g1, fabsf(x - 1.0f), ip);
    ip = fmaf(g2, fabsf(x - 2.0f), ip);
    ip = fmaf(g3, fabsf(x - 3.0f), ip);
    ip = fmaf(g4, fabsf(x - 4.0f), ip);
    float p = tp[t];
    float w = tw[t];
    float d = ip - p;
    num = fmaf(d * d, w, num);
    den += w;
}

#define ELEM4(xv, tv, nm, dn) \
    owe_elem((xv).x, (tv).x, al, be, g0, g1, g2, g3, g4, tp, tw, nm, dn); \
    owe_elem((xv).y, (tv).y, al, be, g0, g1, g2, g3, g4, tp, tw, nm, dn); \
    owe_elem((xv).z, (tv).z, al, be, g0, g1, g2, g3, g4, tp, tw, nm, dn); \
    owe_elem((xv).w, (tv).w, al, be, g0, g1, g2, g3, g4, tp, tw, nm, dn);

__global__ void __launch_bounds__(256, 6)
owe_kernel(const float4* __restrict__ inp4,
           const int4*  __restrict__ tgt4,
           const float* __restrict__ weight,
           const float* __restrict__ dist,
           int n4,
           const float* __restrict__ inp_tail,
           const int*   __restrict__ tgt_tail,
           int tail_start, int n_total,
           float* __restrict__ out) {
    __shared__ float s_coef[8];        // alpha, beta, g0..g4
    __shared__ float s_tp[NREP * 8];   // pcnl[t], replicated
    __shared__ float s_tw[NREP * 8];   // weight[t], replicated

    if (threadIdx.x == 0) {
        float ds[C_CLASSES], cs[C_CLASSES];
        float ext[C_CLASSES + 2], s[C_CLASSES + 1];
        float c = 0.f;
        #pragma unroll
        for (int i = 0; i < C_CLASSES; i++) { ds[i] = dist[i]; c += ds[i]; cs[i] = c; }
        float inv = 1.0f / (2.0f * cs[C_CLASSES - 1] - ds[0] - ds[C_CLASSES - 1]);
        ext[0] = -1.0f / (float)(C_CLASSES - 1);
        #pragma unroll
        for (int i = 0; i < C_CLASSES; i++)
            ext[i + 1] = (2.0f * cs[i] - ds[i] - ds[0]) * inv;
        ext[C_CLASSES + 1] = (float)C_CLASSES / (float)(C_CLASSES - 1);
        #pragma unroll
        for (int j = 0; j <= C_CLASSES; j++)
            s[j] = ext[j + 1] - ext[j];
        float gs = 0.0f;
        #pragma unroll
        for (int k = 0; k < C_CLASSES; k++) {
            float g = 0.5f * (s[k + 1] - s[k]);
            s_coef[2 + k] = g;
            gs += g * (float)k;
        }
        s_coef[1] = 0.5f * (s[0] + s[C_CLASSES]);
        s_coef[0] = ext[1] - gs;
        #pragma unroll
        for (int r = 0; r < NREP; r++) {
            #pragma unroll
            for (int i = 0; i < C_CLASSES; i++) {
                s_tp[r * 8 + i] = ext[i + 1];
                s_tw[r * 8 + i] = weight[i];
            }
        }
    }
    __syncthreads();

    const float al = s_coef[0];
    const float be = s_coef[1];
    const float g0 = s_coef[2];
    const float g1 = s_coef[3];
    const float g2 = s_coef[4];
    const float g3 = s_coef[5];
    const float g4 = s_coef[6];

    const int rep = (threadIdx.x & (NREP - 1)) * 8;
    const float* __restrict__ tp = s_tp + rep;
    const float* __restrict__ tw = s_tw + rep;

    // 4 independent accumulator pairs (one per in-flight vec4 pair).
    float num0 = 0.0f, num1 = 0.0f, num2 = 0.0f, num3 = 0.0f;
    float den0 = 0.0f, den1 = 0.0f, den2 = 0.0f, den3 = 0.0f;

    int tid    = blockIdx.x * blockDim.x + threadIdx.x;
    int stride = gridDim.x * blockDim.x;

    int i = tid;
    // Unroll x4: 8 LDG.128 front-batched (MLP_p1 = 8).
    for (; i + 3 * stride < n4; i += 4 * stride) {
        float4 x0 = inp4[i];
        float4 x1 = inp4[i + stride];
        float4 x2 = inp4[i + 2 * stride];
        float4 x3 = inp4[i + 3 * stride];
        int4   t0 = tgt4[i];
        int4   t1 = tgt4[i + stride];
        int4   t2 = tgt4[i + 2 * stride];
        int4   t3 = tgt4[i + 3 * stride];
        ELEM4(x0, t0, num0, den0)
        ELEM4(x1, t1, num1, den1)
        ELEM4(x2, t2, num2, den2)
        ELEM4(x3, t3, num3, den3)
    }
    for (; i < n4; i += stride) {
        float4 x0 = inp4[i];
        int4   t0 = tgt4[i];
        ELEM4(x0, t0, num0, den0)
    }
    for (int jj = tail_start + tid; jj < n_total; jj += stride) {
        owe_elem(inp_tail[jj], tgt_tail[jj], al, be, g0, g1, g2, g3, g4,
                 tp, tw, num0, den0);
    }

    float num = (num0 + num1) + (num2 + num3);
    float den = (den0 + den1) + (den2 + den3);

    // Warp reduction
    #pragma unroll
    for (int off = 16; off > 0; off >>= 1) {
        num += __shfl_down_sync(0xFFFFFFFFu, num, off);
        den += __shfl_down_sync(0xFFFFFFFFu, den, off);
    }

    // Block reduction
    __shared__ float s_num[8];
    __shared__ float s_den[8];
    int lane = threadIdx.x & 31;
    int warp = threadIdx.x >> 5;
    if (lane == 0) { s_num[warp] = num; s_den[warp] = den; }
    __syncthreads();
    if (warp == 0) {
        float bn = (lane < (blockDim.x >> 5)) ? s_num[lane] : 0.0f;
        float bd = (lane < (blockDim.x >> 5)) ? s_den[lane] : 0.0f;
        #pragma unroll
        for (int off = 4; off > 0; off >>= 1) {
            bn += __shfl_down_sync(0xFFFFFFFFu, bn, off);
            bd += __shfl_down_sync(0xFFFFFFFFu, bd, off);
        }
        if (lane == 0) {
            atomicAdd(&g_acc[0], (double)bn);
            atomicAdd(&g_acc[1], (double)bd);
            __threadfence();
            unsigned done = atomicAdd(&g_count, 1u);
            if (done == gridDim.x - 1) {
                double fn = __longlong_as_double(
                    atomicExch((unsigned long long*)&g_acc[0], 0ULL));
                double fd = __longlong_as_double(
                    atomicExch((unsigned long long*)&g_acc[1], 0ULL));
                out[0] = (float)(fn / fd);
                atomicExch(&g_count, 0u);
            }
        }
    }
}

extern "C" void kernel_launch(void* const* d_in, const int* in_sizes, int n_in,
                              void* d_out, int out_size) {
    const float* inp  = (const float*)d_in[0];
    const int*   tgt  = (const int*)d_in[1];
    const float* wgt  = (const float*)d_in[2];
    const float* dist = (const float*)d_in[3];
    float* out = (float*)d_out;

    int n  = in_sizes[0];
    int n4 = n >> 2;
    int tail_start = n4 << 2;

    const int threads = 256;
    int blocks = 148 * 6;  // 888 blocks, single wave at 6 blocks/SM
    int max_useful = (n4 + threads - 1) / threads;
    if (blocks > max_useful && max_useful > 0) blocks = max_useful;
    if (blocks < 1) blocks = 1;

    owe_kernel<<<blocks, threads>>>((const float4*)inp, (const int4*)tgt,
                                    wgt, dist, n4, inp, tgt, tail_start, n, out);
}